// round 2
// baseline (speedup 1.0000x reference)
#include <cuda_runtime.h>
#include <cuda_bf16.h>
#include <cstdint>

// ---------------------------------------------------------------------------
// Problem constants
// ---------------------------------------------------------------------------
#define BT 4096
#define HDIM 2048
#define VOCAB 32000
#define TILE_M 128
#define TILE_N 256
#define K_CHUNK 64
#define N_KCHUNKS (HDIM / K_CHUNK)        // 32
#define M_TILES (BT / TILE_M)             // 32
#define N_TILES (VOCAB / TILE_N)          // 125
#define IGNORE_INDEX (-100LL)

// idesc: dtype=F32(1<<4), atype=BF16(1<<7), btype=BF16(1<<10), N/8<<17, M/16<<24
#define MMA_IDESC ((1u << 4) | (1u << 7) | (1u << 10) | ((TILE_N / 8) << 17) | ((TILE_M / 16) << 24))

// SMEM layout (dynamic)
#define SM_TMEMPTR 0
#define SM_BAR0 8
#define SM_BAR1 16
#define SM_A 1024                          // 2 x 16384 (128 rows x 128B)
#define SM_B (1024 + 2 * TILE_M * 128)     // 33792, 2 x 32768 (256 rows x 128B)
#define SM_TOTAL (SM_B + 2 * TILE_N * 128) // 99328

// tcgen05 feature gate: only the sm_103a / sm_100a device passes support it.
// The plain compute_103 PTX pass compiles the fallback branch instead.
#if defined(__CUDA_ARCH_FEAT_SM103_ALL) || defined(__CUDA_ARCH_FEAT_SM100_ALL)
#define HAS_TCGEN05 1
#else
#define HAS_TCGEN05 0
#endif

// ---------------------------------------------------------------------------
// Device scratch (static __device__ arrays: allocation-guard-safe)
// ---------------------------------------------------------------------------
__device__ __nv_bfloat16 g_hid_bf[(size_t)BT * HDIM];       // 16.8 MB
__device__ __nv_bfloat16 g_w_bf[(size_t)VOCAB * HDIM];      // 131 MB
__device__ float g_partials[(size_t)N_TILES * BT];          // 2 MB
__device__ float g_tgt[BT];

// ---------------------------------------------------------------------------
// PTX helpers (sm_103a only; macros are inert unless expanded)
// ---------------------------------------------------------------------------
__device__ __forceinline__ uint32_t smem_to_u32(const void* p) {
    uint32_t a;
    asm("{ .reg .u64 t; cvta.to.shared.u64 t, %1; cvt.u32.u64 %0, t; }" : "=r"(a) : "l"(p));
    return a;
}
__device__ __forceinline__ uint32_t elect_one_pred() {
    uint32_t pred;
    asm volatile("{\n\t.reg .pred p;\n\telect.sync _|p, 0xFFFFFFFF;\n\tselp.b32 %0, 1, 0, p;\n\t}" : "=r"(pred));
    return pred;
}
#define TCGEN05_ALLOC(smem_addr, nCols) \
    asm volatile("tcgen05.alloc.cta_group::1.sync.aligned.shared::cta.b32 [%0], %1;" \
                 :: "r"((uint32_t)(smem_addr)), "r"((uint32_t)(nCols)) : "memory")
#define TCGEN05_DEALLOC(tmem_addr, nCols) \
    asm volatile("tcgen05.dealloc.cta_group::1.sync.aligned.b32 %0, %1;" :: "r"(tmem_addr), "r"((uint32_t)(nCols)))
#define TCGEN05_RELINQUISH() \
    asm volatile("tcgen05.relinquish_alloc_permit.cta_group::1.sync.aligned;")
#define TCGEN05_COMMIT(mbar) \
    asm volatile("tcgen05.commit.cta_group::1.mbarrier::arrive::one.shared::cluster.b64 [%0];" \
                 :: "r"((uint32_t)(mbar)) : "memory")
#define TCGEN05_FENCE_AFTER() asm volatile("tcgen05.fence::after_thread_sync;" ::: "memory")
#define TCGEN05_FENCE_BEFORE() asm volatile("tcgen05.fence::before_thread_sync;" ::: "memory")
#define TCGEN05_WAIT_LD() asm volatile("tcgen05.wait::ld.sync.aligned;" ::: "memory")
#define FENCE_PROXY_ASYNC_SHARED() asm volatile("fence.proxy.async.shared::cta;" ::: "memory")
#define MBARRIER_INIT(mbar, cnt) \
    asm volatile("mbarrier.init.shared.b64 [%0], %1;" :: "r"((uint32_t)(mbar)), "r"((uint32_t)(cnt)) : "memory")
#define MBARRIER_INVAL(mbar) \
    asm volatile("mbarrier.inval.shared.b64 [%0];" :: "r"((uint32_t)(mbar)) : "memory")
#define MBARRIER_WAIT_PARITY(mbar, parity) do {                                           \
    uint32_t _m = (uint32_t)(mbar); uint32_t _p = (uint32_t)(parity); uint32_t _d;        \
    asm volatile("{\n\t.reg .pred p;\n\t"                                                 \
        "mbarrier.try_wait.parity.acquire.cta.shared::cta.b64 p, [%1], %2;\n\t"           \
        "selp.b32 %0, 1, 0, p;\n\t}" : "=r"(_d) : "r"(_m), "r"(_p) : "memory");           \
    if (!_d) {                                                                            \
        asm volatile("{\n\t.reg .pred P1;\n\t"                                            \
            "WAIT_LOOP_%=:\n\t"                                                           \
            "mbarrier.try_wait.parity.acquire.cta.shared::cta.b64 P1, [%0], %1, 0x989680;\n\t" \
            "@P1 bra.uni WAIT_DONE_%=;\n\t"                                               \
            "bra.uni WAIT_LOOP_%=;\n\t"                                                   \
            "WAIT_DONE_%=:\n\t}" :: "r"(_m), "r"(_p) : "memory");                         \
    }                                                                                     \
} while (0)
#define TCGEN05_LD_32X32B_X32(r, tmem_addr) \
    asm volatile( \
        "tcgen05.ld.sync.aligned.32x32b.x32.b32 " \
        "{%0, %1, %2, %3, %4, %5, %6, %7, " \
        " %8, %9, %10, %11, %12, %13, %14, %15, " \
        " %16, %17, %18, %19, %20, %21, %22, %23, " \
        " %24, %25, %26, %27, %28, %29, %30, %31}, [%32];" \
        : "=r"((r)[0]),  "=r"((r)[1]),  "=r"((r)[2]),  "=r"((r)[3]), \
          "=r"((r)[4]),  "=r"((r)[5]),  "=r"((r)[6]),  "=r"((r)[7]), \
          "=r"((r)[8]),  "=r"((r)[9]),  "=r"((r)[10]), "=r"((r)[11]), \
          "=r"((r)[12]), "=r"((r)[13]), "=r"((r)[14]), "=r"((r)[15]), \
          "=r"((r)[16]), "=r"((r)[17]), "=r"((r)[18]), "=r"((r)[19]), \
          "=r"((r)[20]), "=r"((r)[21]), "=r"((r)[22]), "=r"((r)[23]), \
          "=r"((r)[24]), "=r"((r)[25]), "=r"((r)[26]), "=r"((r)[27]), \
          "=r"((r)[28]), "=r"((r)[29]), "=r"((r)[30]), "=r"((r)[31]) \
        : "r"(tmem_addr))

// SMEM descriptor: SW128 K-major, version=1 (Blackwell), SBO=64, LBO=1
static constexpr uint64_t SMEM_DESC_BASE_SW128 =
    (uint64_t(2) << 61) | (uint64_t(1) << 46) | (uint64_t(64) << 32) | (uint64_t(1) << 16);
#define MAKE_SMEM_DESC(base_addr) (SMEM_DESC_BASE_SW128 | ((uint64_t)((base_addr) >> 4) & 0x3FFF))
#define SMEM_SWIZZLE_128B(off) ((off) ^ (((off) >> 3) & 0x70))

#if HAS_TCGEN05
// cg1 SS-mode bf16 MMA (A-desc, B-desc both in SMEM)
__device__ __forceinline__ void mma_f16_ss(uint32_t d_tmem, uint64_t a_desc, uint64_t b_desc,
                                           uint32_t idesc, uint32_t enable_d) {
    asm volatile(
        "{\n\t.reg .pred p;\n\t"
        "setp.ne.u32 p, %5, 0;\n\t"
        "tcgen05.mma.cta_group::1.kind::f16 [%0], %1, %2, %3, {%4, %4, %4, %4}, p;\n\t}"
        :: "r"(d_tmem), "l"(a_desc), "l"(b_desc), "r"(idesc), "r"(0u), "r"(enable_d)
        : "memory");
}
#endif

// ---------------------------------------------------------------------------
// Kernel 1: fp32 -> bf16 conversion into device scratch (halves GEMM traffic)
// ---------------------------------------------------------------------------
__global__ void convert_kernel(const float* __restrict__ hid, const float* __restrict__ w) {
    const size_t nh = (size_t)BT * HDIM / 4;
    const size_t nw = (size_t)VOCAB * HDIM / 4;
    const size_t total = nh + nw;
    size_t stride = (size_t)gridDim.x * blockDim.x;
    for (size_t i = (size_t)blockIdx.x * blockDim.x + threadIdx.x; i < total; i += stride) {
        const float4* src;
        __nv_bfloat16* dst;
        size_t j;
        if (i < nh) { src = (const float4*)hid; dst = g_hid_bf; j = i; }
        else        { src = (const float4*)w;   dst = g_w_bf;   j = i - nh; }
        float4 v = src[j];
        __nv_bfloat162 lo = __floats2bfloat162_rn(v.x, v.y);
        __nv_bfloat162 hi = __floats2bfloat162_rn(v.z, v.w);
        *(__nv_bfloat162*)(dst + j * 4)     = lo;
        *(__nv_bfloat162*)(dst + j * 4 + 2) = hi;
    }
}

// ---------------------------------------------------------------------------
// Kernel 2: zero target-logit scratch (rerun every launch for determinism)
// ---------------------------------------------------------------------------
__global__ void zero_tgt_kernel() {
    int i = blockIdx.x * blockDim.x + threadIdx.x;
    if (i < BT) g_tgt[i] = 0.0f;
}

// ---------------------------------------------------------------------------
// Kernel 3: tcgen05 bf16 GEMM (128x256 tiles) + fused exp/row-sum epilogue
// ---------------------------------------------------------------------------
__device__ __forceinline__ void load_tile_chunk(char* smem, int tid,
                                                const __nv_bfloat16* Ag,
                                                const __nv_bfloat16* Bg,
                                                int k0, int buf) {
    // A: 128 rows x 64 bf16 = 1024 uint4; B: 256 rows x 64 bf16 = 2048 uint4
    char* abase = smem + SM_A + buf * (TILE_M * 128);
    char* bbase = smem + SM_B + buf * (TILE_N * 128);
#pragma unroll
    for (int l = 0; l < 8; l++) {
        int i = tid + l * 128;
        int row = i >> 3, c = i & 7;
        uint4 v = *(const uint4*)(Ag + (size_t)row * HDIM + k0 + c * 8);
        uint32_t off = row * 128 + c * 16;
        *(uint4*)(abase + SMEM_SWIZZLE_128B(off)) = v;
    }
#pragma unroll
    for (int l = 0; l < 16; l++) {
        int i = tid + l * 128;
        int row = i >> 3, c = i & 7;
        uint4 v = *(const uint4*)(Bg + (size_t)row * HDIM + k0 + c * 8);
        uint32_t off = row * 128 + c * 16;
        *(uint4*)(bbase + SMEM_SWIZZLE_128B(off)) = v;
    }
}

__global__ void __launch_bounds__(128, 1)
gemm_ce_kernel(const long long* __restrict__ targets) {
    extern __shared__ char smem[];
    int tid = threadIdx.x;

    // consecutive blocks share the same weight (N) panel -> L2 reuse of B within a wave
    int n_tile = blockIdx.x / M_TILES;
    int m_tile = blockIdx.x % M_TILES;
    int m0 = m_tile * TILE_M;
    int n0 = n_tile * TILE_N;

#if HAS_TCGEN05
    uint32_t sb = smem_to_u32(smem);
    int wid = tid >> 5;

    if (wid == 0) {
        TCGEN05_ALLOC(sb + SM_TMEMPTR, 256);
        TCGEN05_RELINQUISH();
    }
    __syncthreads();
    uint32_t tmem;
    asm volatile("ld.shared.b32 %0, [%1];" : "=r"(tmem) : "r"(sb + SM_TMEMPTR));

    if (tid == 0) {
        MBARRIER_INIT(sb + SM_BAR0, 1);
        MBARRIER_INIT(sb + SM_BAR1, 1);
    }
    __syncthreads();

    const __nv_bfloat16* Ag = g_hid_bf + (size_t)m0 * HDIM;
    const __nv_bfloat16* Bg = g_w_bf + (size_t)n0 * HDIM;

    // prologue
    load_tile_chunk(smem, tid, Ag, Bg, 0, 0);
    FENCE_PROXY_ASYNC_SHARED();
    __syncthreads();

    int ph0 = 0, ph1 = 0;
#pragma unroll 1
    for (int kc = 0; kc < N_KCHUNKS; kc++) {
        int cur = kc & 1;
        if (wid == 0) {
            if (elect_one_pred()) {
                uint64_t ad = MAKE_SMEM_DESC(sb + SM_A + cur * (TILE_M * 128));
                uint64_t bd = MAKE_SMEM_DESC(sb + SM_B + cur * (TILE_N * 128));
#pragma unroll
                for (int s = 0; s < 4; s++)  // 4 x K=16 within the 64-col chunk
                    mma_f16_ss(tmem, ad + s * 2, bd + s * 2, MMA_IDESC,
                               (kc > 0 || s > 0) ? 1u : 0u);
                TCGEN05_COMMIT(sb + (cur ? SM_BAR1 : SM_BAR0));
            }
        }
        // wait for the MMA that was reading the OTHER buffer before overwriting it
        if (kc >= 1) {
            if ((cur ^ 1) == 0) { MBARRIER_WAIT_PARITY(sb + SM_BAR0, ph0); ph0 ^= 1; }
            else                { MBARRIER_WAIT_PARITY(sb + SM_BAR1, ph1); ph1 ^= 1; }
        }
        if (kc + 1 < N_KCHUNKS) {
            load_tile_chunk(smem, tid, Ag, Bg, (kc + 1) * K_CHUNK, cur ^ 1);
            FENCE_PROXY_ASYNC_SHARED();
        }
        __syncthreads();
    }
    // last chunk (kc=31) committed on BAR1
    MBARRIER_WAIT_PARITY(sb + SM_BAR1, ph1);
    TCGEN05_FENCE_AFTER();

    // Epilogue: thread tid == output row (wid*32+lid == TMEM lane).
    long long t = targets[m0 + tid];
    float sum = 0.0f;
    float tval = 0.0f;
#pragma unroll 1
    for (int c = 0; c < TILE_N / 32; c++) {
        uint32_t regs[32];
        TCGEN05_LD_32X32B_X32(regs, tmem + c * 32);
        TCGEN05_WAIT_LD();
#pragma unroll
        for (int j = 0; j < 32; j++) {
            float v = __uint_as_float(regs[j]);
            sum += __expf(v);
            if ((long long)(n0 + c * 32 + j) == t) tval = v;
        }
    }
    TCGEN05_FENCE_BEFORE();
    g_partials[(size_t)n_tile * BT + m0 + tid] = sum;
    if (t >= (long long)n0 && t < (long long)(n0 + TILE_N)) g_tgt[m0 + tid] = tval;

    __syncthreads();
    if (tid == 0) { MBARRIER_INVAL(sb + SM_BAR0); MBARRIER_INVAL(sb + SM_BAR1); }
    __syncthreads();
    if (wid == 0) TCGEN05_DEALLOC(tmem, 256);

#else  // ------- non-sm_103a fallback (only runs if PTX-JIT path is used) ----
    // smem: A chunk 128x64 bf16 @0 (16KB), B chunk 32x64 bf16 @16384 (4KB)
    __nv_bfloat16* As = (__nv_bfloat16*)smem;
    __nv_bfloat16* Bs = (__nv_bfloat16*)(smem + 16384);
    const __nv_bfloat16* Ag = g_hid_bf + (size_t)m0 * HDIM;

    long long t = targets[m0 + tid];
    float sum = 0.0f, tval = 0.0f;
    for (int cg = 0; cg < TILE_N / 32; cg++) {
        float acc[32];
#pragma unroll
        for (int j = 0; j < 32; j++) acc[j] = 0.0f;
        const __nv_bfloat16* Bg = g_w_bf + (size_t)(n0 + cg * 32) * HDIM;
        for (int kc = 0; kc < N_KCHUNKS; kc++) {
            __syncthreads();
            int k0 = kc * K_CHUNK;
#pragma unroll
            for (int l = 0; l < 8; l++) {
                int i = tid + l * 128;
                int row = i >> 3, c = i & 7;
                *(uint4*)(As + row * 64 + c * 8) =
                    *(const uint4*)(Ag + (size_t)row * HDIM + k0 + c * 8);
            }
#pragma unroll
            for (int l = 0; l < 2; l++) {
                int i = tid + l * 128;
                int row = i >> 3, c = i & 7;
                *(uint4*)(Bs + row * 64 + c * 8) =
                    *(const uint4*)(Bg + (size_t)row * HDIM + k0 + c * 8);
            }
            __syncthreads();
            for (int k = 0; k < K_CHUNK; k++) {
                float a = __bfloat162float(As[tid * 64 + k]);
#pragma unroll
                for (int j = 0; j < 32; j++)
                    acc[j] += a * __bfloat162float(Bs[j * 64 + k]);
            }
        }
#pragma unroll
        for (int j = 0; j < 32; j++) {
            float v = acc[j];
            sum += __expf(v);
            if ((long long)(n0 + cg * 32 + j) == t) tval = v;
        }
    }
    g_partials[(size_t)n_tile * BT + m0 + tid] = sum;
    if (t >= (long long)n0 && t < (long long)(n0 + TILE_N)) g_tgt[m0 + tid] = tval;
#endif
}

// ---------------------------------------------------------------------------
// Kernel 4: deterministic final reduction -> scalar loss
// ---------------------------------------------------------------------------
__global__ void reduce_kernel(const long long* __restrict__ targets, float* __restrict__ out) {
    __shared__ float sl[256];
    __shared__ int sc[256];
    int tid = threadIdx.x;
    float loss = 0.0f;
    int cnt = 0;
    for (int r = tid; r < BT; r += 256) {
        float s = 0.0f;
#pragma unroll 1
        for (int nt = 0; nt < N_TILES; nt++) s += g_partials[(size_t)nt * BT + r];
        long long t = targets[r];
        if (t != IGNORE_INDEX) {
            loss += logf(s) - g_tgt[r];
            cnt++;
        }
    }
    sl[tid] = loss;
    sc[tid] = cnt;
    __syncthreads();
    for (int o = 128; o > 0; o >>= 1) {
        if (tid < o) { sl[tid] += sl[tid + o]; sc[tid] += sc[tid + o]; }
        __syncthreads();
    }
    if (tid == 0) out[0] = sl[0] / (float)(sc[0] > 0 ? sc[0] : 1);
}

// ---------------------------------------------------------------------------
// Launch
// ---------------------------------------------------------------------------
extern "C" void kernel_launch(void* const* d_in, const int* in_sizes, int n_in,
                              void* d_out, int out_size) {
    const float* hidden = (const float*)d_in[0];
    const float* weight = (const float*)d_in[1];
    const long long* targets = (const long long*)d_in[2];
    float* out = (float*)d_out;

    cudaFuncSetAttribute(gemm_ce_kernel, cudaFuncAttributeMaxDynamicSharedMemorySize, SM_TOTAL);

    convert_kernel<<<2048, 256>>>(hidden, weight);
    zero_tgt_kernel<<<(BT + 255) / 256, 256>>>();
    gemm_ce_kernel<<<M_TILES * N_TILES, 128, SM_TOTAL>>>(targets);
    reduce_kernel<<<1, 256>>>(targets, out);
}

// round 3
// speedup vs baseline: 2.0714x; 2.0714x over previous
#include <cuda_runtime.h>
#include <cuda_bf16.h>
#include <cstdint>

// ---------------------------------------------------------------------------
// Problem constants
// ---------------------------------------------------------------------------
#define BT 4096
#define HDIM 2048
#define VOCAB 32000
#define TILE_M 128
#define TILE_N 256
#define K_CHUNK 64
#define N_KCHUNKS (HDIM / K_CHUNK)        // 32
#define M_TILES (BT / TILE_M)             // 32
#define N_TILES (VOCAB / TILE_N)          // 125
#define IGNORE_INDEX (-100LL)
#define RL_BLOCKS 16

// idesc: dtype=F32(1<<4), atype=BF16(1<<7), btype=BF16(1<<10), N/8<<17, M/16<<24
#define MMA_IDESC ((1u << 4) | (1u << 7) | (1u << 10) | ((TILE_N / 8) << 17) | ((TILE_M / 16) << 24))

// SMEM layout (dynamic)
#define SM_TMEMPTR 0
#define SM_BAR0 8
#define SM_BAR1 16
#define SM_A 1024                          // 2 x 16384 (128 rows x 128B)
#define SM_B (1024 + 2 * TILE_M * 128)     // 33792, 2 x 32768 (256 rows x 128B)
#define SM_TOTAL (SM_B + 2 * TILE_N * 128) // 99328

// tcgen05 feature gate: only the sm_103a / sm_100a device passes support it.
// The plain compute_103 PTX pass compiles the fallback branch instead.
#if defined(__CUDA_ARCH_FEAT_SM103_ALL) || defined(__CUDA_ARCH_FEAT_SM100_ALL)
#define HAS_TCGEN05 1
#else
#define HAS_TCGEN05 0
#endif

// ---------------------------------------------------------------------------
// Device scratch (static __device__ arrays: allocation-guard-safe)
// ---------------------------------------------------------------------------
__device__ __nv_bfloat16 g_hid_bf[(size_t)BT * HDIM];       // 16.8 MB
__device__ __nv_bfloat16 g_w_bf[(size_t)VOCAB * HDIM];      // 131 MB
__device__ float g_partials[(size_t)N_TILES * BT];          // 2 MB
__device__ float g_tgt[BT];
__device__ float g_blocksum[RL_BLOCKS];
__device__ int   g_blockcnt[RL_BLOCKS];

// ---------------------------------------------------------------------------
// PTX helpers (sm_103a only; macros are inert unless expanded)
// ---------------------------------------------------------------------------
__device__ __forceinline__ uint32_t smem_to_u32(const void* p) {
    uint32_t a;
    asm("{ .reg .u64 t; cvta.to.shared.u64 t, %1; cvt.u32.u64 %0, t; }" : "=r"(a) : "l"(p));
    return a;
}
__device__ __forceinline__ uint32_t elect_one_pred() {
    uint32_t pred;
    asm volatile("{\n\t.reg .pred p;\n\telect.sync _|p, 0xFFFFFFFF;\n\tselp.b32 %0, 1, 0, p;\n\t}" : "=r"(pred));
    return pred;
}
#define TCGEN05_ALLOC(smem_addr, nCols) \
    asm volatile("tcgen05.alloc.cta_group::1.sync.aligned.shared::cta.b32 [%0], %1;" \
                 :: "r"((uint32_t)(smem_addr)), "r"((uint32_t)(nCols)) : "memory")
#define TCGEN05_DEALLOC(tmem_addr, nCols) \
    asm volatile("tcgen05.dealloc.cta_group::1.sync.aligned.b32 %0, %1;" :: "r"(tmem_addr), "r"((uint32_t)(nCols)))
#define TCGEN05_RELINQUISH() \
    asm volatile("tcgen05.relinquish_alloc_permit.cta_group::1.sync.aligned;")
#define TCGEN05_COMMIT(mbar) \
    asm volatile("tcgen05.commit.cta_group::1.mbarrier::arrive::one.shared::cluster.b64 [%0];" \
                 :: "r"((uint32_t)(mbar)) : "memory")
#define TCGEN05_FENCE_AFTER() asm volatile("tcgen05.fence::after_thread_sync;" ::: "memory")
#define TCGEN05_FENCE_BEFORE() asm volatile("tcgen05.fence::before_thread_sync;" ::: "memory")
#define TCGEN05_WAIT_LD() asm volatile("tcgen05.wait::ld.sync.aligned;" ::: "memory")
#define FENCE_PROXY_ASYNC_SHARED() asm volatile("fence.proxy.async.shared::cta;" ::: "memory")
#define MBARRIER_INIT(mbar, cnt) \
    asm volatile("mbarrier.init.shared.b64 [%0], %1;" :: "r"((uint32_t)(mbar)), "r"((uint32_t)(cnt)) : "memory")
#define MBARRIER_INVAL(mbar) \
    asm volatile("mbarrier.inval.shared.b64 [%0];" :: "r"((uint32_t)(mbar)) : "memory")
#define MBARRIER_WAIT_PARITY(mbar, parity) do {                                           \
    uint32_t _m = (uint32_t)(mbar); uint32_t _p = (uint32_t)(parity); uint32_t _d;        \
    asm volatile("{\n\t.reg .pred p;\n\t"                                                 \
        "mbarrier.try_wait.parity.acquire.cta.shared::cta.b64 p, [%1], %2;\n\t"           \
        "selp.b32 %0, 1, 0, p;\n\t}" : "=r"(_d) : "r"(_m), "r"(_p) : "memory");           \
    if (!_d) {                                                                            \
        asm volatile("{\n\t.reg .pred P1;\n\t"                                            \
            "WAIT_LOOP_%=:\n\t"                                                           \
            "mbarrier.try_wait.parity.acquire.cta.shared::cta.b64 P1, [%0], %1, 0x989680;\n\t" \
            "@P1 bra.uni WAIT_DONE_%=;\n\t"                                               \
            "bra.uni WAIT_LOOP_%=;\n\t"                                                   \
            "WAIT_DONE_%=:\n\t}" :: "r"(_m), "r"(_p) : "memory");                         \
    }                                                                                     \
} while (0)
#define TCGEN05_LD_32X32B_X32(r, tmem_addr) \
    asm volatile( \
        "tcgen05.ld.sync.aligned.32x32b.x32.b32 " \
        "{%0, %1, %2, %3, %4, %5, %6, %7, " \
        " %8, %9, %10, %11, %12, %13, %14, %15, " \
        " %16, %17, %18, %19, %20, %21, %22, %23, " \
        " %24, %25, %26, %27, %28, %29, %30, %31}, [%32];" \
        : "=r"((r)[0]),  "=r"((r)[1]),  "=r"((r)[2]),  "=r"((r)[3]), \
          "=r"((r)[4]),  "=r"((r)[5]),  "=r"((r)[6]),  "=r"((r)[7]), \
          "=r"((r)[8]),  "=r"((r)[9]),  "=r"((r)[10]), "=r"((r)[11]), \
          "=r"((r)[12]), "=r"((r)[13]), "=r"((r)[14]), "=r"((r)[15]), \
          "=r"((r)[16]), "=r"((r)[17]), "=r"((r)[18]), "=r"((r)[19]), \
          "=r"((r)[20]), "=r"((r)[21]), "=r"((r)[22]), "=r"((r)[23]), \
          "=r"((r)[24]), "=r"((r)[25]), "=r"((r)[26]), "=r"((r)[27]), \
          "=r"((r)[28]), "=r"((r)[29]), "=r"((r)[30]), "=r"((r)[31]) \
        : "r"(tmem_addr))

// SMEM descriptor: SW128 K-major, version=1 (Blackwell), SBO=64, LBO=1
static constexpr uint64_t SMEM_DESC_BASE_SW128 =
    (uint64_t(2) << 61) | (uint64_t(1) << 46) | (uint64_t(64) << 32) | (uint64_t(1) << 16);
#define MAKE_SMEM_DESC(base_addr) (SMEM_DESC_BASE_SW128 | ((uint64_t)((base_addr) >> 4) & 0x3FFF))
#define SMEM_SWIZZLE_128B(off) ((off) ^ (((off) >> 3) & 0x70))

#if HAS_TCGEN05
// cg1 SS-mode bf16 MMA (A-desc, B-desc both in SMEM)
__device__ __forceinline__ void mma_f16_ss(uint32_t d_tmem, uint64_t a_desc, uint64_t b_desc,
                                           uint32_t idesc, uint32_t enable_d) {
    asm volatile(
        "{\n\t.reg .pred p;\n\t"
        "setp.ne.u32 p, %5, 0;\n\t"
        "tcgen05.mma.cta_group::1.kind::f16 [%0], %1, %2, %3, {%4, %4, %4, %4}, p;\n\t}"
        :: "r"(d_tmem), "l"(a_desc), "l"(b_desc), "r"(idesc), "r"(0u), "r"(enable_d)
        : "memory");
}
#endif

// ---------------------------------------------------------------------------
// Kernel 1: fp32 -> bf16 conversion into device scratch (halves GEMM traffic)
// ---------------------------------------------------------------------------
__global__ void convert_kernel(const float* __restrict__ hid, const float* __restrict__ w) {
    const size_t nh = (size_t)BT * HDIM / 4;
    const size_t nw = (size_t)VOCAB * HDIM / 4;
    const size_t total = nh + nw;
    size_t stride = (size_t)gridDim.x * blockDim.x;
    for (size_t i = (size_t)blockIdx.x * blockDim.x + threadIdx.x; i < total; i += stride) {
        const float4* src;
        __nv_bfloat16* dst;
        size_t j;
        if (i < nh) { src = (const float4*)hid; dst = g_hid_bf; j = i; }
        else        { src = (const float4*)w;   dst = g_w_bf;   j = i - nh; }
        float4 v = src[j];
        __nv_bfloat162 lo = __floats2bfloat162_rn(v.x, v.y);
        __nv_bfloat162 hi = __floats2bfloat162_rn(v.z, v.w);
        *(__nv_bfloat162*)(dst + j * 4)     = lo;
        *(__nv_bfloat162*)(dst + j * 4 + 2) = hi;
    }
}

// ---------------------------------------------------------------------------
// Kernel 2: zero target-logit scratch (rerun every launch for determinism)
// ---------------------------------------------------------------------------
__global__ void zero_tgt_kernel() {
    int i = blockIdx.x * blockDim.x + threadIdx.x;
    if (i < BT) g_tgt[i] = 0.0f;
}

// ---------------------------------------------------------------------------
// Kernel 3: tcgen05 bf16 GEMM (128x256 tiles) + fused exp/row-sum epilogue
// ---------------------------------------------------------------------------
__device__ __forceinline__ void load_tile_chunk(char* smem, int tid,
                                                const __nv_bfloat16* Ag,
                                                const __nv_bfloat16* Bg,
                                                int k0, int buf) {
    // A: 128 rows x 64 bf16 = 1024 uint4; B: 256 rows x 64 bf16 = 2048 uint4
    char* abase = smem + SM_A + buf * (TILE_M * 128);
    char* bbase = smem + SM_B + buf * (TILE_N * 128);
#pragma unroll
    for (int l = 0; l < 8; l++) {
        int i = tid + l * 128;
        int row = i >> 3, c = i & 7;
        uint4 v = *(const uint4*)(Ag + (size_t)row * HDIM + k0 + c * 8);
        uint32_t off = row * 128 + c * 16;
        *(uint4*)(abase + SMEM_SWIZZLE_128B(off)) = v;
    }
#pragma unroll
    for (int l = 0; l < 16; l++) {
        int i = tid + l * 128;
        int row = i >> 3, c = i & 7;
        uint4 v = *(const uint4*)(Bg + (size_t)row * HDIM + k0 + c * 8);
        uint32_t off = row * 128 + c * 16;
        *(uint4*)(bbase + SMEM_SWIZZLE_128B(off)) = v;
    }
}

__global__ void __launch_bounds__(128, 1)
gemm_ce_kernel(const long long* __restrict__ targets) {
    extern __shared__ char smem[];
    int tid = threadIdx.x;

    // consecutive blocks share the same weight (N) panel -> L2 reuse of B within a wave
    int n_tile = blockIdx.x / M_TILES;
    int m_tile = blockIdx.x % M_TILES;
    int m0 = m_tile * TILE_M;
    int n0 = n_tile * TILE_N;

#if HAS_TCGEN05
    uint32_t sb = smem_to_u32(smem);
    int wid = tid >> 5;

    if (wid == 0) {
        TCGEN05_ALLOC(sb + SM_TMEMPTR, 256);
        TCGEN05_RELINQUISH();
    }
    __syncthreads();
    uint32_t tmem;
    asm volatile("ld.shared.b32 %0, [%1];" : "=r"(tmem) : "r"(sb + SM_TMEMPTR));

    if (tid == 0) {
        MBARRIER_INIT(sb + SM_BAR0, 1);
        MBARRIER_INIT(sb + SM_BAR1, 1);
    }
    __syncthreads();

    const __nv_bfloat16* Ag = g_hid_bf + (size_t)m0 * HDIM;
    const __nv_bfloat16* Bg = g_w_bf + (size_t)n0 * HDIM;

    // prologue
    load_tile_chunk(smem, tid, Ag, Bg, 0, 0);
    FENCE_PROXY_ASYNC_SHARED();
    __syncthreads();

    int ph0 = 0, ph1 = 0;
#pragma unroll 1
    for (int kc = 0; kc < N_KCHUNKS; kc++) {
        int cur = kc & 1;
        if (wid == 0) {
            if (elect_one_pred()) {
                uint64_t ad = MAKE_SMEM_DESC(sb + SM_A + cur * (TILE_M * 128));
                uint64_t bd = MAKE_SMEM_DESC(sb + SM_B + cur * (TILE_N * 128));
#pragma unroll
                for (int s = 0; s < 4; s++)  // 4 x K=16 within the 64-col chunk
                    mma_f16_ss(tmem, ad + s * 2, bd + s * 2, MMA_IDESC,
                               (kc > 0 || s > 0) ? 1u : 0u);
                TCGEN05_COMMIT(sb + (cur ? SM_BAR1 : SM_BAR0));
            }
        }
        // wait for the MMA that was reading the OTHER buffer before overwriting it
        if (kc >= 1) {
            if ((cur ^ 1) == 0) { MBARRIER_WAIT_PARITY(sb + SM_BAR0, ph0); ph0 ^= 1; }
            else                { MBARRIER_WAIT_PARITY(sb + SM_BAR1, ph1); ph1 ^= 1; }
        }
        if (kc + 1 < N_KCHUNKS) {
            load_tile_chunk(smem, tid, Ag, Bg, (kc + 1) * K_CHUNK, cur ^ 1);
            FENCE_PROXY_ASYNC_SHARED();
        }
        __syncthreads();
    }
    // last chunk (kc=31) committed on BAR1
    MBARRIER_WAIT_PARITY(sb + SM_BAR1, ph1);
    TCGEN05_FENCE_AFTER();

    // Epilogue: thread tid == output row (wid*32+lid == TMEM lane).
    long long t = targets[m0 + tid];
    float sum = 0.0f;
    float tval = 0.0f;
#pragma unroll 1
    for (int c = 0; c < TILE_N / 32; c++) {
        uint32_t regs[32];
        TCGEN05_LD_32X32B_X32(regs, tmem + c * 32);
        TCGEN05_WAIT_LD();
#pragma unroll
        for (int j = 0; j < 32; j++) {
            float v = __uint_as_float(regs[j]);
            sum += __expf(v);
            if ((long long)(n0 + c * 32 + j) == t) tval = v;
        }
    }
    TCGEN05_FENCE_BEFORE();
    g_partials[(size_t)n_tile * BT + m0 + tid] = sum;
    if (t >= (long long)n0 && t < (long long)(n0 + TILE_N)) g_tgt[m0 + tid] = tval;

    __syncthreads();
    if (tid == 0) { MBARRIER_INVAL(sb + SM_BAR0); MBARRIER_INVAL(sb + SM_BAR1); }
    __syncthreads();
    if (wid == 0) TCGEN05_DEALLOC(tmem, 256);

#else  // ------- non-sm_103a fallback (only runs if PTX-JIT path is used) ----
    // smem: A chunk 128x64 bf16 @0 (16KB), B chunk 32x64 bf16 @16384 (4KB)
    __nv_bfloat16* As = (__nv_bfloat16*)smem;
    __nv_bfloat16* Bs = (__nv_bfloat16*)(smem + 16384);
    const __nv_bfloat16* Ag = g_hid_bf + (size_t)m0 * HDIM;

    long long t = targets[m0 + tid];
    float sum = 0.0f, tval = 0.0f;
    for (int cg = 0; cg < TILE_N / 32; cg++) {
        float acc[32];
#pragma unroll
        for (int j = 0; j < 32; j++) acc[j] = 0.0f;
        const __nv_bfloat16* Bg = g_w_bf + (size_t)(n0 + cg * 32) * HDIM;
        for (int kc = 0; kc < N_KCHUNKS; kc++) {
            __syncthreads();
            int k0 = kc * K_CHUNK;
#pragma unroll
            for (int l = 0; l < 8; l++) {
                int i = tid + l * 128;
                int row = i >> 3, c = i & 7;
                *(uint4*)(As + row * 64 + c * 8) =
                    *(const uint4*)(Ag + (size_t)row * HDIM + k0 + c * 8);
            }
#pragma unroll
            for (int l = 0; l < 2; l++) {
                int i = tid + l * 128;
                int row = i >> 3, c = i & 7;
                *(uint4*)(Bs + row * 64 + c * 8) =
                    *(const uint4*)(Bg + (size_t)row * HDIM + k0 + c * 8);
            }
            __syncthreads();
            for (int k = 0; k < K_CHUNK; k++) {
                float a = __bfloat162float(As[tid * 64 + k]);
#pragma unroll
                for (int j = 0; j < 32; j++)
                    acc[j] += a * __bfloat162float(Bs[j * 64 + k]);
            }
        }
#pragma unroll
        for (int j = 0; j < 32; j++) {
            float v = acc[j];
            sum += __expf(v);
            if ((long long)(n0 + cg * 32 + j) == t) tval = v;
        }
    }
    g_partials[(size_t)n_tile * BT + m0 + tid] = sum;
    if (t >= (long long)n0 && t < (long long)(n0 + TILE_N)) g_tgt[m0 + tid] = tval;
#endif
}

// ---------------------------------------------------------------------------
// Kernel 4a: per-row loss, whole-chip parallel (16 blocks x 256 threads).
// Thread r sums its row's 125 tile-partials; reads are coalesced across the
// warp (consecutive r at fixed nt = contiguous 128B lines). Block tree-reduce
// -> one (sum, count) per block. Deterministic (fixed order, no atomics).
// ---------------------------------------------------------------------------
__global__ void row_loss_kernel(const long long* __restrict__ targets) {
    __shared__ float sl[256];
    __shared__ int sc[256];
    int tid = threadIdx.x;
    int r = blockIdx.x * 256 + tid;

    float s = 0.0f;
#pragma unroll 5
    for (int nt = 0; nt < N_TILES; nt++) s += g_partials[(size_t)nt * BT + r];

    long long t = targets[r];
    bool valid = (t != IGNORE_INDEX);
    sl[tid] = valid ? (logf(s) - g_tgt[r]) : 0.0f;
    sc[tid] = valid ? 1 : 0;
    __syncthreads();
#pragma unroll
    for (int o = 128; o > 0; o >>= 1) {
        if (tid < o) { sl[tid] += sl[tid + o]; sc[tid] += sc[tid + o]; }
        __syncthreads();
    }
    if (tid == 0) { g_blocksum[blockIdx.x] = sl[0]; g_blockcnt[blockIdx.x] = sc[0]; }
}

// ---------------------------------------------------------------------------
// Kernel 4b: final scalar combine (16 values)
// ---------------------------------------------------------------------------
__global__ void final_kernel(float* __restrict__ out) {
    if (threadIdx.x == 0) {
        float s = 0.0f;
        int c = 0;
#pragma unroll
        for (int b = 0; b < RL_BLOCKS; b++) { s += g_blocksum[b]; c += g_blockcnt[b]; }
        out[0] = s / (float)(c > 0 ? c : 1);
    }
}

// ---------------------------------------------------------------------------
// Launch
// ---------------------------------------------------------------------------
extern "C" void kernel_launch(void* const* d_in, const int* in_sizes, int n_in,
                              void* d_out, int out_size) {
    const float* hidden = (const float*)d_in[0];
    const float* weight = (const float*)d_in[1];
    const long long* targets = (const long long*)d_in[2];
    float* out = (float*)d_out;

    cudaFuncSetAttribute(gemm_ce_kernel, cudaFuncAttributeMaxDynamicSharedMemorySize, SM_TOTAL);

    convert_kernel<<<2048, 256>>>(hidden, weight);
    zero_tgt_kernel<<<(BT + 255) / 256, 256>>>();
    gemm_ce_kernel<<<M_TILES * N_TILES, 128, SM_TOTAL>>>(targets);
    row_loss_kernel<<<RL_BLOCKS, 256>>>(targets);
    final_kernel<<<1, 32>>>(out);
}